// round 11
// baseline (speedup 1.0000x reference)
#include <cuda_runtime.h>

// Problem constants (fixed by setup_inputs): B=8, N=16384, K=64
#define BB    8
#define NN    16384
#define KK    64
#define MTOT  (BB * NN)            // 131072 points total
#define NROWS (BB * KK)            // 512 (b,k) rows
#define NHALF (NROWS * 2)          // 1024 half-row BN units
// inv = -1/(2*sigma^2) = -12.5 ;  C = inv * log2(e)
#define CLOG2 (-18.033688011112043f)

#define GRID  444                  // 3 CTAs/SM on 148 SMs, all co-resident
#define TPB   256                  // 8 warps
#define PTS_A 32
#define NUNITA (MTOT / PTS_A)      // 4096 stage-A warp units
#define PTS_B 16
#define NUNITB (MTOT / PTS_B)      // 8192 stage-B warp units

// Scratch (no cudaMalloc allowed)
__device__ float  g_h[(size_t)MTOT * KK];   // 33.5 MB: h[b][j][k], k contiguous
__device__ double g_sum[KK];
__device__ double g_ssum[KK];
__device__ unsigned g_workA;
__device__ unsigned g_workB;
__device__ unsigned g_arrive;               // grid barrier, monotonic across replays
__device__ volatile unsigned g_release;

__device__ __forceinline__ float ex2f(float x) {
    float r;
    asm("ex2.approx.ftz.f32 %0, %1;" : "=f"(r) : "f"(x));
    return r;
}

// Software grid barrier. Monotonic epoch counters -> safe across graph replays.
__device__ __forceinline__ void gsync() {
    __syncthreads();
    if (threadIdx.x == 0) {
        __threadfence();
        unsigned t = atomicAdd(&g_arrive, 1u);
        unsigned ep = t / GRID + 1u;
        if (t % GRID == GRID - 1u) {
            g_release = ep;
        } else {
            while (g_release < ep) { __nanosleep(64); }
        }
        __threadfence();
    }
    __syncthreads();
}

__global__ void __launch_bounds__(TPB, 3) fkc_fused(
    const float* __restrict__ normals,
    const void*  __restrict__ nidx,
    const float* __restrict__ wa,
    const float* __restrict__ wb,
    const float* __restrict__ gamma,
    const float* __restrict__ beta,
    float* __restrict__ out)
{
    __shared__ float sT[8][PTS_B * 66];   // per-warp transpose tiles (33.8 KB)
    __shared__ int   sIdx32;

    const int tid  = threadIdx.x;
    const int warp = tid >> 5;
    const int lane = tid & 31;
    float* sTw = sT[warp];

    if (tid == 0) {
        // Probe int32 (JAX default) vs int64 neighbor_idx
        int is32 = 0;
        const long long* p = (const long long*)nidx;
        for (int j = 0; j < 8; j++) {
            long long v = p[j];
            if (v < 0 || v >= NN) is32 = 1;
        }
        sIdx32 = is32;
    }
    if (blockIdx.x == 0 && tid < KK) { g_sum[tid] = 0.0; g_ssum[tid] = 0.0; }

    // Per-lane weights: k = lane (low half) and k = lane+32 (high half)
    // w' = -2C * w ; we = exp2(C*||w||^2)/16
    float WxL[4], WyL[4], WzL[4], WeL[4];
    float WxH[4], WyH[4], WzH[4], WeH[4];
#pragma unroll
    for (int m = 0; m < 4; m++) {
#pragma unroll
        for (int half = 0; half < 2; half++) {
            int k = lane + half * 32;
            float a = __ldg(wa + k * 4 + m), b = __ldg(wb + k * 4 + m);
            float sa, ca, sb, cb;
            sincosf(a, &sa, &ca);
            sincosf(b, &sb, &cb);
            float wx = sa * cb, wy = sa * sb, wz = ca;
            float W2 = wx * wx + wy * wy + wz * wz;
            const float s = -2.0f * CLOG2;
            float we = exp2f(CLOG2 * W2) * (1.0f / 16.0f);
            if (half == 0) { WxL[m] = wx * s; WyL[m] = wy * s; WzL[m] = wz * s; WeL[m] = we; }
            else           { WxH[m] = wx * s; WyH[m] = wy * s; WzH[m] = wz * s; WeH[m] = we; }
        }
    }
    __syncthreads();
    const int idx32 = sIdx32;

    // ---- Stage A: h[b][j][k] = sum_m exp2(f.w'_km + C||f||^2) * we_km ----
    // Warp-autonomous work stealing; lane = k / k+32.
    for (;;) {
        unsigned u;
        if (lane == 0) u = atomicAdd(&g_workA, 1u);
        u = __shfl_sync(0xFFFFFFFFu, u, 0);
        if (u >= NUNITA) break;

        int base = (int)u * PTS_A;
        int b  = base >> 14;
        int n0 = base & (NN - 1);
        const float* nb = normals + (size_t)b * (3 * NN);
        float* hp = g_h + ((size_t)b * NN + n0) * KK + lane;

#pragma unroll 4
        for (int p = 0; p < PTS_A; p++) {
            int n = n0 + p;
            float x = __ldg(nb + n);
            float y = __ldg(nb + NN + n);
            float z = __ldg(nb + 2 * NN + n);
            float cf2 = CLOG2 * fmaf(x, x, fmaf(y, y, z * z));
            float slo = 0.f, shi = 0.f;
#pragma unroll
            for (int m = 0; m < 4; m++) {
                slo = fmaf(ex2f(fmaf(x, WxL[m], fmaf(y, WyL[m], fmaf(z, WzL[m], cf2)))), WeL[m], slo);
                shi = fmaf(ex2f(fmaf(x, WxH[m], fmaf(y, WyH[m], fmaf(z, WzH[m], cf2)))), WeH[m], shi);
            }
            hp[(size_t)p * KK]      = slo;
            hp[(size_t)p * KK + 32] = shi;
        }
    }

    gsync();   // all h written, stats zeroed
    if (blockIdx.x == 0 && tid == 0) g_workA = 0;   // reset for next replay

    // ---- Stage B: feat = gather-sum of 4 h rows; transpose-write + stats --
    // Warp-autonomous; lane = k / k+32; per-warp smem tile; no __syncthreads.
    float s_lo = 0.f, ss_lo = 0.f, s_hi = 0.f, ss_hi = 0.f;
    for (;;) {
        unsigned u;
        if (lane == 0) u = atomicAdd(&g_workB, 1u);
        u = __shfl_sync(0xFFFFFFFFu, u, 0);
        if (u >= NUNITB) break;

        int base = (int)u * PTS_B;
        int b  = base >> 14;
        int n0 = base & (NN - 1);
        const float* hb = g_h + (size_t)b * NN * KK;

        // Neighbor triples for the 16 points live in lanes 0..15 (dup in 16..31)
        int j1, j2, j3;
        {
            int il = lane & 15;
            size_t rowbase = ((size_t)b * NN + n0 + il) * 3;
            if (idx32) {
                const int* ip = (const int*)nidx + rowbase;
                j1 = ip[0]; j2 = ip[1]; j3 = ip[2];
            } else {
                const long long* ip = (const long long*)nidx + rowbase;
                j1 = (int)ip[0]; j2 = (int)ip[1]; j3 = (int)ip[2];
            }
        }

#pragma unroll
        for (int pt0 = 0; pt0 < PTS_B; pt0 += 4) {
            float L0[4], L1[4], L2[4], L3[4];
            float H0[4], H1[4], H2[4], H3[4];
#pragma unroll
            for (int q = 0; q < 4; q++) {
                int pt = pt0 + q;
                int a1 = __shfl_sync(0xFFFFFFFFu, j1, pt);
                int a2 = __shfl_sync(0xFFFFFFFFu, j2, pt);
                int a3 = __shfl_sync(0xFFFFFFFFu, j3, pt);
                const float* r0 = hb + (size_t)(n0 + pt) * KK + lane;
                const float* r1 = hb + (size_t)a1 * KK + lane;
                const float* r2 = hb + (size_t)a2 * KK + lane;
                const float* r3 = hb + (size_t)a3 * KK + lane;
                L0[q] = __ldg(r0);      L1[q] = __ldg(r1);
                L2[q] = __ldg(r2);      L3[q] = __ldg(r3);
                H0[q] = __ldg(r0 + 32); H1[q] = __ldg(r1 + 32);
                H2[q] = __ldg(r2 + 32); H3[q] = __ldg(r3 + 32);
            }
#pragma unroll
            for (int q = 0; q < 4; q++) {
                int pt = pt0 + q;
                float vlo = (L0[q] + L1[q]) + (L2[q] + L3[q]);
                float vhi = (H0[q] + H1[q]) + (H2[q] + H3[q]);
                sTw[pt * 66 + lane]      = vlo;
                sTw[pt * 66 + 32 + lane] = vhi;
                s_lo += vlo; ss_lo = fmaf(vlo, vlo, ss_lo);
                s_hi += vhi; ss_hi = fmaf(vhi, vhi, ss_hi);
            }
        }
        __syncwarp();

        // Transposed flush: lanes 0-15 row r, lanes 16-31 row r+1 (conflict-free
        // via stride-66 padding); stores are 64B-aligned 16-float runs.
        {
            int nn = lane & 15;
            int rh = lane >> 4;
            float* ob = out + (size_t)b * KK * NN + n0 + nn;
#pragma unroll
            for (int r2 = 0; r2 < KK; r2 += 2) {
                int r = r2 + rh;
                ob[(size_t)r * NN] = sTw[nn * 66 + r];
            }
        }
        __syncwarp();
    }

    // Per-warp stats flush: lane owns k=lane and k=lane+32
    atomicAdd(&g_sum[lane],       (double)s_lo);
    atomicAdd(&g_ssum[lane],      (double)ss_lo);
    atomicAdd(&g_sum[lane + 32],  (double)s_hi);
    atomicAdd(&g_ssum[lane + 32], (double)ss_hi);

    gsync();   // all stats accumulated
    if (blockIdx.x == 0 && tid == 0) g_workB = 0;   // reset for next replay

    // ---- Stage C: BN + ReLU in place (L2-resident) ------------------------
    for (int h = blockIdx.x; h < NHALF; h += GRID) {
        int r = h >> 1;
        int kk = r & (KK - 1);
        double mean = g_sum[kk] * (1.0 / MTOT);
        double var  = g_ssum[kk] * (1.0 / MTOT) - mean * mean;
        float sc = __ldg(gamma + kk) * rsqrtf((float)var + 1e-5f);
        float sh = __ldg(beta + kk) - (float)mean * sc;
        float4* p4 = (float4*)(out + (size_t)r * NN + (h & 1) * (NN / 2));
#pragma unroll
        for (int i = 0; i < NN / 8 / TPB; i++) {   // 8 iterations
            float4 v = p4[i * TPB + tid];
            v.x = fmaxf(fmaf(v.x, sc, sh), 0.f);
            v.y = fmaxf(fmaf(v.y, sc, sh), 0.f);
            v.z = fmaxf(fmaf(v.z, sc, sh), 0.f);
            v.w = fmaxf(fmaf(v.w, sc, sh), 0.f);
            p4[i * TPB + tid] = v;
        }
    }
}

extern "C" void kernel_launch(void* const* d_in, const int* in_sizes, int n_in,
                              void* d_out, int out_size) {
    const float* normals = (const float*)d_in[0];
    const void*  nidx    = d_in[1];
    const float* wa      = (const float*)d_in[2];
    const float* wb      = (const float*)d_in[3];
    const float* gamma   = (const float*)d_in[4];
    const float* beta    = (const float*)d_in[5];
    float* out = (float*)d_out;

    fkc_fused<<<GRID, TPB>>>(normals, nidx, wa, wb, gamma, beta, out);
}

// round 12
// speedup vs baseline: 1.0081x; 1.0081x over previous
#include <cuda_runtime.h>

// Problem constants (fixed by setup_inputs): B=8, N=16384, K=64
#define BB    8
#define NN    16384
#define KK    64
#define MTOT  (BB * NN)            // 131072 points total
#define NROWS (BB * KK)            // 512 (b,k) rows
#define NHALF (NROWS * 2)          // 1024 half-row BN units
// inv = -1/(2*sigma^2) = -12.5 ;  C = inv * log2(e)
#define CLOG2 (-18.033688011112043f)

#define GRID  444                  // 3 CTAs/SM on 148 SMs, all co-resident
#define TPB   256                  // 8 warps
#define PTS_A 32
#define NUNITA (MTOT / PTS_A)      // 4096 stage-A warp units
#define PTS_B 16
#define NUNITB (MTOT / PTS_B)      // 8192 stage-B warp units

// Scratch (no cudaMalloc allowed)
__device__ float  g_h[(size_t)MTOT * KK];   // 33.5 MB: h[b][j][k], k contiguous
__device__ double g_sum[KK];
__device__ double g_ssum[KK];
__device__ unsigned g_workA;
__device__ unsigned g_workB;
__device__ unsigned g_arrive;               // grid barrier, monotonic across replays
__device__ volatile unsigned g_release;

__device__ __forceinline__ float ex2f(float x) {
    float r;
    asm("ex2.approx.ftz.f32 %0, %1;" : "=f"(r) : "f"(x));
    return r;
}

// Software grid barrier. Monotonic epoch counters -> safe across graph replays.
__device__ __forceinline__ void gsync() {
    __syncthreads();
    if (threadIdx.x == 0) {
        __threadfence();
        unsigned t = atomicAdd(&g_arrive, 1u);
        unsigned ep = t / GRID + 1u;
        if (t % GRID == GRID - 1u) {
            g_release = ep;
        } else {
            while (g_release < ep) { __nanosleep(64); }
        }
        __threadfence();
    }
    __syncthreads();
}

__global__ void __launch_bounds__(TPB, 3) fkc_fused(
    const float* __restrict__ normals,
    const void*  __restrict__ nidx,
    const float* __restrict__ wa,
    const float* __restrict__ wb,
    const float* __restrict__ gamma,
    const float* __restrict__ beta,
    float* __restrict__ out)
{
    __shared__ float sT[8][PTS_B * 66];   // per-warp transpose tiles (33.8 KB)
    __shared__ int   sIdx32;

    const int tid  = threadIdx.x;
    const int warp = tid >> 5;
    const int lane = tid & 31;
    float* sTw = sT[warp];

    if (tid == 0) {
        // Probe int32 (JAX default) vs int64 neighbor_idx
        int is32 = 0;
        const long long* p = (const long long*)nidx;
        for (int j = 0; j < 8; j++) {
            long long v = p[j];
            if (v < 0 || v >= NN) is32 = 1;
        }
        sIdx32 = is32;
    }
    if (blockIdx.x == 0 && tid < KK) { g_sum[tid] = 0.0; g_ssum[tid] = 0.0; }

    // Per-lane weights: k = lane (low half) and k = lane+32 (high half)
    // w' = -2C * w ; we = exp2(C*||w||^2)/16
    float WxL[4], WyL[4], WzL[4], WeL[4];
    float WxH[4], WyH[4], WzH[4], WeH[4];
#pragma unroll
    for (int m = 0; m < 4; m++) {
#pragma unroll
        for (int half = 0; half < 2; half++) {
            int k = lane + half * 32;
            float a = __ldg(wa + k * 4 + m), b = __ldg(wb + k * 4 + m);
            float sa, ca, sb, cb;
            sincosf(a, &sa, &ca);
            sincosf(b, &sb, &cb);
            float wx = sa * cb, wy = sa * sb, wz = ca;
            float W2 = wx * wx + wy * wy + wz * wz;
            const float s = -2.0f * CLOG2;
            float we = exp2f(CLOG2 * W2) * (1.0f / 16.0f);
            if (half == 0) { WxL[m] = wx * s; WyL[m] = wy * s; WzL[m] = wz * s; WeL[m] = we; }
            else           { WxH[m] = wx * s; WyH[m] = wy * s; WzH[m] = wz * s; WeH[m] = we; }
        }
    }
    __syncthreads();
    const int idx32 = sIdx32;

    // ---- Stage A: h[b][j][k] = sum_m exp2(f.w'_km + C||f||^2) * we_km ----
    // Warp-autonomous work stealing; lane = k / k+32.
    for (;;) {
        unsigned u;
        if (lane == 0) u = atomicAdd(&g_workA, 1u);
        u = __shfl_sync(0xFFFFFFFFu, u, 0);
        if (u >= NUNITA) break;

        int base = (int)u * PTS_A;
        int b  = base >> 14;
        int n0 = base & (NN - 1);
        const float* nb = normals + (size_t)b * (3 * NN);
        float* hp = g_h + ((size_t)b * NN + n0) * KK + lane;

#pragma unroll 4
        for (int p = 0; p < PTS_A; p++) {
            int n = n0 + p;
            float x = __ldg(nb + n);
            float y = __ldg(nb + NN + n);
            float z = __ldg(nb + 2 * NN + n);
            float cf2 = CLOG2 * fmaf(x, x, fmaf(y, y, z * z));
            float slo = 0.f, shi = 0.f;
#pragma unroll
            for (int m = 0; m < 4; m++) {
                slo = fmaf(ex2f(fmaf(x, WxL[m], fmaf(y, WyL[m], fmaf(z, WzL[m], cf2)))), WeL[m], slo);
                shi = fmaf(ex2f(fmaf(x, WxH[m], fmaf(y, WyH[m], fmaf(z, WzH[m], cf2)))), WeH[m], shi);
            }
            hp[(size_t)p * KK]      = slo;
            hp[(size_t)p * KK + 32] = shi;
        }
    }

    gsync();   // all h written, stats zeroed
    if (blockIdx.x == 0 && tid == 0) g_workA = 0;   // reset for next replay

    // ---- Stage B: feat = gather-sum of 4 h rows; transpose-write + stats --
    // Warp-autonomous; lane = k / k+32; per-warp smem tile; no __syncthreads.
    float s_lo = 0.f, ss_lo = 0.f, s_hi = 0.f, ss_hi = 0.f;
    for (;;) {
        unsigned u;
        if (lane == 0) u = atomicAdd(&g_workB, 1u);
        u = __shfl_sync(0xFFFFFFFFu, u, 0);
        if (u >= NUNITB) break;

        int base = (int)u * PTS_B;
        int b  = base >> 14;
        int n0 = base & (NN - 1);
        const float* hb = g_h + (size_t)b * NN * KK;

        // Neighbor triples for the 16 points live in lanes 0..15 (dup in 16..31)
        int j1, j2, j3;
        {
            int il = lane & 15;
            size_t rowbase = ((size_t)b * NN + n0 + il) * 3;
            if (idx32) {
                const int* ip = (const int*)nidx + rowbase;
                j1 = ip[0]; j2 = ip[1]; j3 = ip[2];
            } else {
                const long long* ip = (const long long*)nidx + rowbase;
                j1 = (int)ip[0]; j2 = (int)ip[1]; j3 = (int)ip[2];
            }
        }

#pragma unroll
        for (int pt0 = 0; pt0 < PTS_B; pt0 += 4) {
            float L0[4], L1[4], L2[4], L3[4];
            float H0[4], H1[4], H2[4], H3[4];
#pragma unroll
            for (int q = 0; q < 4; q++) {
                int pt = pt0 + q;
                int a1 = __shfl_sync(0xFFFFFFFFu, j1, pt);
                int a2 = __shfl_sync(0xFFFFFFFFu, j2, pt);
                int a3 = __shfl_sync(0xFFFFFFFFu, j3, pt);
                const float* r0 = hb + (size_t)(n0 + pt) * KK + lane;
                const float* r1 = hb + (size_t)a1 * KK + lane;
                const float* r2 = hb + (size_t)a2 * KK + lane;
                const float* r3 = hb + (size_t)a3 * KK + lane;
                L0[q] = __ldg(r0);      L1[q] = __ldg(r1);
                L2[q] = __ldg(r2);      L3[q] = __ldg(r3);
                H0[q] = __ldg(r0 + 32); H1[q] = __ldg(r1 + 32);
                H2[q] = __ldg(r2 + 32); H3[q] = __ldg(r3 + 32);
            }
#pragma unroll
            for (int q = 0; q < 4; q++) {
                int pt = pt0 + q;
                float vlo = (L0[q] + L1[q]) + (L2[q] + L3[q]);
                float vhi = (H0[q] + H1[q]) + (H2[q] + H3[q]);
                sTw[pt * 66 + lane]      = vlo;
                sTw[pt * 66 + 32 + lane] = vhi;
                s_lo += vlo; ss_lo = fmaf(vlo, vlo, ss_lo);
                s_hi += vhi; ss_hi = fmaf(vhi, vhi, ss_hi);
            }
        }
        __syncwarp();

        // Transposed flush: lanes 0-15 row r, lanes 16-31 row r+1 (conflict-free
        // via stride-66 padding); stores are 64B-aligned 16-float runs.
        {
            int nn = lane & 15;
            int rh = lane >> 4;
            float* ob = out + (size_t)b * KK * NN + n0 + nn;
#pragma unroll
            for (int r2 = 0; r2 < KK; r2 += 2) {
                int r = r2 + rh;
                ob[(size_t)r * NN] = sTw[nn * 66 + r];
            }
        }
        __syncwarp();
    }

    // Per-warp stats flush: lane owns k=lane and k=lane+32
    atomicAdd(&g_sum[lane],       (double)s_lo);
    atomicAdd(&g_ssum[lane],      (double)ss_lo);
    atomicAdd(&g_sum[lane + 32],  (double)s_hi);
    atomicAdd(&g_ssum[lane + 32], (double)ss_hi);

    gsync();   // all stats accumulated
    if (blockIdx.x == 0 && tid == 0) g_workB = 0;   // reset for next replay

    // ---- Stage C: BN + ReLU in place (L2-resident) ------------------------
    for (int h = blockIdx.x; h < NHALF; h += GRID) {
        int r = h >> 1;
        int kk = r & (KK - 1);
        double mean = g_sum[kk] * (1.0 / MTOT);
        double var  = g_ssum[kk] * (1.0 / MTOT) - mean * mean;
        float sc = __ldg(gamma + kk) * rsqrtf((float)var + 1e-5f);
        float sh = __ldg(beta + kk) - (float)mean * sc;
        float4* p4 = (float4*)(out + (size_t)r * NN + (h & 1) * (NN / 2));
#pragma unroll
        for (int i = 0; i < NN / 8 / TPB; i++) {   // 8 iterations
            float4 v = p4[i * TPB + tid];
            v.x = fmaxf(fmaf(v.x, sc, sh), 0.f);
            v.y = fmaxf(fmaf(v.y, sc, sh), 0.f);
            v.z = fmaxf(fmaf(v.z, sc, sh), 0.f);
            v.w = fmaxf(fmaf(v.w, sc, sh), 0.f);
            p4[i * TPB + tid] = v;
        }
    }
}

extern "C" void kernel_launch(void* const* d_in, const int* in_sizes, int n_in,
                              void* d_out, int out_size) {
    const float* normals = (const float*)d_in[0];
    const void*  nidx    = d_in[1];
    const float* wa      = (const float*)d_in[2];
    const float* wb      = (const float*)d_in[3];
    const float* gamma   = (const float*)d_in[4];
    const float* beta    = (const float*)d_in[5];
    float* out = (float*)d_out;

    fkc_fused<<<GRID, TPB>>>(normals, nidx, wa, wb, gamma, beta, out);
}

// round 13
// speedup vs baseline: 1.0098x; 1.0017x over previous
#include <cuda_runtime.h>

// Problem constants (fixed by setup_inputs): B=8, N=16384, K=64
#define BB    8
#define NN    16384
#define KK    64
#define MTOT  (BB * NN)            // 131072 points total
#define NROWS (BB * KK)            // 512 (b,k) rows
#define NHALF (NROWS * 2)          // 1024 half-row BN units
// inv = -1/(2*sigma^2) = -12.5 ;  C = inv * log2(e)
#define CLOG2 (-18.033688011112043f)

#define GRID  444                  // 3 CTAs/SM on 148 SMs, all co-resident
#define TPB   256                  // 8 warps
#define PTS_A 32
#define NUNITA (MTOT / PTS_A)      // 4096 stage-A warp units
#define PTS_B 16
#define NUNITB (MTOT / PTS_B)      // 8192 stage-B warp units

// Scratch (no cudaMalloc allowed)
__device__ float  g_h[(size_t)MTOT * KK];   // 33.5 MB: h[b][j][k], k contiguous
__device__ double g_sum[KK];
__device__ double g_ssum[KK];
__device__ unsigned g_workA;
__device__ unsigned g_workB;
__device__ unsigned g_arrive;               // grid barrier, monotonic across replays
__device__ volatile unsigned g_release;

__device__ __forceinline__ float ex2f(float x) {
    float r;
    asm("ex2.approx.ftz.f32 %0, %1;" : "=f"(r) : "f"(x));
    return r;
}

// Software grid barrier. Monotonic epoch counters -> safe across graph replays.
__device__ __forceinline__ void gsync() {
    __syncthreads();
    if (threadIdx.x == 0) {
        __threadfence();
        unsigned t = atomicAdd(&g_arrive, 1u);
        unsigned ep = t / GRID + 1u;
        if (t % GRID == GRID - 1u) {
            g_release = ep;
        } else {
            while (g_release < ep) { __nanosleep(64); }
        }
        __threadfence();
    }
    __syncthreads();
}

__global__ void __launch_bounds__(TPB, 3) fkc_fused(
    const float* __restrict__ normals,
    const void*  __restrict__ nidx,
    const float* __restrict__ wa,
    const float* __restrict__ wb,
    const float* __restrict__ gamma,
    const float* __restrict__ beta,
    float* __restrict__ out)
{
    __shared__ float sT[8][PTS_B * 66];   // per-warp transpose tiles (33.8 KB)
    __shared__ int   sIdx32;

    const int tid  = threadIdx.x;
    const int warp = tid >> 5;
    const int lane = tid & 31;
    float* sTw = sT[warp];

    if (tid == 0) {
        // Probe int32 (JAX default) vs int64 neighbor_idx
        int is32 = 0;
        const long long* p = (const long long*)nidx;
        for (int j = 0; j < 8; j++) {
            long long v = p[j];
            if (v < 0 || v >= NN) is32 = 1;
        }
        sIdx32 = is32;
    }
    if (blockIdx.x == 0 && tid < KK) { g_sum[tid] = 0.0; g_ssum[tid] = 0.0; }

    // Per-lane weights: k = lane (low half) and k = lane+32 (high half)
    // w' = -2C * w ; we = exp2(C*||w||^2)/16
    float WxL[4], WyL[4], WzL[4], WeL[4];
    float WxH[4], WyH[4], WzH[4], WeH[4];
#pragma unroll
    for (int m = 0; m < 4; m++) {
#pragma unroll
        for (int half = 0; half < 2; half++) {
            int k = lane + half * 32;
            float a = __ldg(wa + k * 4 + m), b = __ldg(wb + k * 4 + m);
            float sa, ca, sb, cb;
            sincosf(a, &sa, &ca);
            sincosf(b, &sb, &cb);
            float wx = sa * cb, wy = sa * sb, wz = ca;
            float W2 = wx * wx + wy * wy + wz * wz;
            const float s = -2.0f * CLOG2;
            float we = exp2f(CLOG2 * W2) * (1.0f / 16.0f);
            if (half == 0) { WxL[m] = wx * s; WyL[m] = wy * s; WzL[m] = wz * s; WeL[m] = we; }
            else           { WxH[m] = wx * s; WyH[m] = wy * s; WzH[m] = wz * s; WeH[m] = we; }
        }
    }
    __syncthreads();
    const int idx32 = sIdx32;

    // ---- Stage A: h[b][j][k] = sum_m exp2(f.w'_km + C||f||^2) * we_km ----
    // Warp-autonomous work stealing; lane = k / k+32.
    for (;;) {
        unsigned u;
        if (lane == 0) u = atomicAdd(&g_workA, 1u);
        u = __shfl_sync(0xFFFFFFFFu, u, 0);
        if (u >= NUNITA) break;

        int base = (int)u * PTS_A;
        int b  = base >> 14;
        int n0 = base & (NN - 1);
        const float* nb = normals + (size_t)b * (3 * NN);
        float* hp = g_h + ((size_t)b * NN + n0) * KK + lane;

#pragma unroll 4
        for (int p = 0; p < PTS_A; p++) {
            int n = n0 + p;
            float x = __ldg(nb + n);
            float y = __ldg(nb + NN + n);
            float z = __ldg(nb + 2 * NN + n);
            float cf2 = CLOG2 * fmaf(x, x, fmaf(y, y, z * z));
            float slo = 0.f, shi = 0.f;
#pragma unroll
            for (int m = 0; m < 4; m++) {
                slo = fmaf(ex2f(fmaf(x, WxL[m], fmaf(y, WyL[m], fmaf(z, WzL[m], cf2)))), WeL[m], slo);
                shi = fmaf(ex2f(fmaf(x, WxH[m], fmaf(y, WyH[m], fmaf(z, WzH[m], cf2)))), WeH[m], shi);
            }
            hp[(size_t)p * KK]      = slo;
            hp[(size_t)p * KK + 32] = shi;
        }
    }

    gsync();   // all h written, stats zeroed
    if (blockIdx.x == 0 && tid == 0) g_workA = 0;   // reset for next replay

    // ---- Stage B: feat = gather-sum of 4 h rows; transpose-write + stats --
    // Warp-autonomous; lane = k / k+32; per-warp smem tile; no __syncthreads.
    float s_lo = 0.f, ss_lo = 0.f, s_hi = 0.f, ss_hi = 0.f;
    for (;;) {
        unsigned u;
        if (lane == 0) u = atomicAdd(&g_workB, 1u);
        u = __shfl_sync(0xFFFFFFFFu, u, 0);
        if (u >= NUNITB) break;

        int base = (int)u * PTS_B;
        int b  = base >> 14;
        int n0 = base & (NN - 1);
        const float* hb = g_h + (size_t)b * NN * KK;

        // Neighbor triples for the 16 points live in lanes 0..15 (dup in 16..31)
        int j1, j2, j3;
        {
            int il = lane & 15;
            size_t rowbase = ((size_t)b * NN + n0 + il) * 3;
            if (idx32) {
                const int* ip = (const int*)nidx + rowbase;
                j1 = ip[0]; j2 = ip[1]; j3 = ip[2];
            } else {
                const long long* ip = (const long long*)nidx + rowbase;
                j1 = (int)ip[0]; j2 = (int)ip[1]; j3 = (int)ip[2];
            }
        }

#pragma unroll
        for (int pt0 = 0; pt0 < PTS_B; pt0 += 4) {
            float L0[4], L1[4], L2[4], L3[4];
            float H0[4], H1[4], H2[4], H3[4];
#pragma unroll
            for (int q = 0; q < 4; q++) {
                int pt = pt0 + q;
                int a1 = __shfl_sync(0xFFFFFFFFu, j1, pt);
                int a2 = __shfl_sync(0xFFFFFFFFu, j2, pt);
                int a3 = __shfl_sync(0xFFFFFFFFu, j3, pt);
                const float* r0 = hb + (size_t)(n0 + pt) * KK + lane;
                const float* r1 = hb + (size_t)a1 * KK + lane;
                const float* r2 = hb + (size_t)a2 * KK + lane;
                const float* r3 = hb + (size_t)a3 * KK + lane;
                L0[q] = __ldg(r0);      L1[q] = __ldg(r1);
                L2[q] = __ldg(r2);      L3[q] = __ldg(r3);
                H0[q] = __ldg(r0 + 32); H1[q] = __ldg(r1 + 32);
                H2[q] = __ldg(r2 + 32); H3[q] = __ldg(r3 + 32);
            }
#pragma unroll
            for (int q = 0; q < 4; q++) {
                int pt = pt0 + q;
                float vlo = (L0[q] + L1[q]) + (L2[q] + L3[q]);
                float vhi = (H0[q] + H1[q]) + (H2[q] + H3[q]);
                sTw[pt * 66 + lane]      = vlo;
                sTw[pt * 66 + 32 + lane] = vhi;
                s_lo += vlo; ss_lo = fmaf(vlo, vlo, ss_lo);
                s_hi += vhi; ss_hi = fmaf(vhi, vhi, ss_hi);
            }
        }
        __syncwarp();

        // Transposed flush: lanes 0-15 row r, lanes 16-31 row r+1 (conflict-free
        // via stride-66 padding); stores are 64B-aligned 16-float runs.
        {
            int nn = lane & 15;
            int rh = lane >> 4;
            float* ob = out + (size_t)b * KK * NN + n0 + nn;
#pragma unroll
            for (int r2 = 0; r2 < KK; r2 += 2) {
                int r = r2 + rh;
                ob[(size_t)r * NN] = sTw[nn * 66 + r];
            }
        }
        __syncwarp();
    }

    // Per-warp stats flush: lane owns k=lane and k=lane+32
    atomicAdd(&g_sum[lane],       (double)s_lo);
    atomicAdd(&g_ssum[lane],      (double)ss_lo);
    atomicAdd(&g_sum[lane + 32],  (double)s_hi);
    atomicAdd(&g_ssum[lane + 32], (double)ss_hi);

    gsync();   // all stats accumulated
    if (blockIdx.x == 0 && tid == 0) g_workB = 0;   // reset for next replay

    // ---- Stage C: BN + ReLU in place (L2-resident) ------------------------
    for (int h = blockIdx.x; h < NHALF; h += GRID) {
        int r = h >> 1;
        int kk = r & (KK - 1);
        double mean = g_sum[kk] * (1.0 / MTOT);
        double var  = g_ssum[kk] * (1.0 / MTOT) - mean * mean;
        float sc = __ldg(gamma + kk) * rsqrtf((float)var + 1e-5f);
        float sh = __ldg(beta + kk) - (float)mean * sc;
        float4* p4 = (float4*)(out + (size_t)r * NN + (h & 1) * (NN / 2));
#pragma unroll
        for (int i = 0; i < NN / 8 / TPB; i++) {   // 8 iterations
            float4 v = p4[i * TPB + tid];
            v.x = fmaxf(fmaf(v.x, sc, sh), 0.f);
            v.y = fmaxf(fmaf(v.y, sc, sh), 0.f);
            v.z = fmaxf(fmaf(v.z, sc, sh), 0.f);
            v.w = fmaxf(fmaf(v.w, sc, sh), 0.f);
            p4[i * TPB + tid] = v;
        }
    }
}

extern "C" void kernel_launch(void* const* d_in, const int* in_sizes, int n_in,
                              void* d_out, int out_size) {
    const float* normals = (const float*)d_in[0];
    const void*  nidx    = d_in[1];
    const float* wa      = (const float*)d_in[2];
    const float* wb      = (const float*)d_in[3];
    const float* gamma   = (const float*)d_in[4];
    const float* beta    = (const float*)d_in[5];
    float* out = (float*)d_out;

    fkc_fused<<<GRID, TPB>>>(normals, nidx, wa, wb, gamma, beta, out);
}